// round 8
// baseline (speedup 1.0000x reference)
#include <cuda_runtime.h>
#include <cstdint>
#include <math.h>

#define T_STEPS 512
#define BATCH   64
#define DIN     256
#define HID     512
#define NGATE4  2048   // 4*H
#define KDH     768    // D+H

#define HP       132   // h chunk row pitch
#define WS_PITCH 516
#define GS_PITCH 17

#define N_REC    128   // recurrent CTAs (bids 0..127)
#define N_PROD   64    // producer CTAs (bids 128..191)
#define N_JOBS   4096  // 16 n-tiles x 256 m-tiles

// -------- device scratch --------
__device__ float g_xg[(size_t)T_STEPS * BATCH * NGATE4];
__device__ float g_h[2][BATCH * HID];
__device__ unsigned int g_ctr;
__device__ unsigned int g_xgdone[256];   // per m-tile-row (2 timesteps) counters

__device__ __forceinline__ float fsigm(float x) {
    return __fdividef(1.0f, 1.0f + __expf(-x));
}
__device__ __forceinline__ float ftanh(float x) {
    float e = __expf(2.0f * x);
    return 1.0f - __fdividef(2.0f, e + 1.0f);
}

// -------- init: reset counters + h0 --------
__global__ void init_kernel() {
    int idx = blockIdx.x * blockDim.x + threadIdx.x;
    if (idx == 0) g_ctr = 0u;
    if (idx < 256) g_xgdone[idx] = 0u;
    int total = 2 * BATCH * HID;
    for (int i = idx; i < total; i += gridDim.x * blockDim.x)
        ((float*)g_h)[i] = 0.0f;
}

// -------- producer: one 128x128 xgemm tile (As/Bs in caller smem) --------
__device__ void xgemm_job(float* As, float* Bs, int nBase, int mBase,
                          const float* __restrict__ X,
                          const float* __restrict__ W,
                          const float* __restrict__ bias, int tid)
{
    // As/Bs: each [2][8][128] floats
    const int loadRow = tid >> 1;
    const int loadCol = (tid & 1) * 4;
    const float* pA = X + (size_t)(mBase + loadRow) * DIN + loadCol;
    const int wrow  = (nBase + loadRow) & 511;
    const float* pB = W + (size_t)wrow * KDH + loadCol;

    float4 a = *(const float4*)pA;
    float4 b = *(const float4*)pB;

    const int tx = tid & 15, ty = tid >> 4;

    float acc[8][8];
#pragma unroll
    for (int i = 0; i < 8; ++i)
#pragma unroll
        for (int j = 0; j < 8; ++j) acc[i][j] = 0.0f;

    As[0 * 1024 + (loadCol + 0) * 128 + loadRow] = a.x;
    As[0 * 1024 + (loadCol + 1) * 128 + loadRow] = a.y;
    As[0 * 1024 + (loadCol + 2) * 128 + loadRow] = a.z;
    As[0 * 1024 + (loadCol + 3) * 128 + loadRow] = a.w;
    Bs[0 * 1024 + (loadCol + 0) * 128 + loadRow] = b.x;
    Bs[0 * 1024 + (loadCol + 1) * 128 + loadRow] = b.y;
    Bs[0 * 1024 + (loadCol + 2) * 128 + loadRow] = b.z;
    Bs[0 * 1024 + (loadCol + 3) * 128 + loadRow] = b.w;
    __syncthreads();

    for (int kt = 0; kt < 32; ++kt) {
        const int cur = kt & 1;
        if (kt < 31) {
            a = *(const float4*)(pA + (kt + 1) * 8);
            b = *(const float4*)(pB + (kt + 1) * 8);
        }
#pragma unroll
        for (int k = 0; k < 8; ++k) {
            float ar[8], br[8];
            *(float4*)&ar[0] = *(const float4*)&As[cur * 1024 + k * 128 + ty * 4];
            *(float4*)&ar[4] = *(const float4*)&As[cur * 1024 + k * 128 + 64 + ty * 4];
            *(float4*)&br[0] = *(const float4*)&Bs[cur * 1024 + k * 128 + tx * 4];
            *(float4*)&br[4] = *(const float4*)&Bs[cur * 1024 + k * 128 + 64 + tx * 4];
#pragma unroll
            for (int i = 0; i < 8; ++i)
#pragma unroll
                for (int j = 0; j < 8; ++j)
                    acc[i][j] = fmaf(ar[i], br[j], acc[i][j]);
        }
        if (kt < 31) {
            const int nxt = cur ^ 1;
            As[nxt * 1024 + (loadCol + 0) * 128 + loadRow] = a.x;
            As[nxt * 1024 + (loadCol + 1) * 128 + loadRow] = a.y;
            As[nxt * 1024 + (loadCol + 2) * 128 + loadRow] = a.z;
            As[nxt * 1024 + (loadCol + 3) * 128 + loadRow] = a.w;
            Bs[nxt * 1024 + (loadCol + 0) * 128 + loadRow] = b.x;
            Bs[nxt * 1024 + (loadCol + 1) * 128 + loadRow] = b.y;
            Bs[nxt * 1024 + (loadCol + 2) * 128 + loadRow] = b.z;
            Bs[nxt * 1024 + (loadCol + 3) * 128 + loadRow] = b.w;
            __syncthreads();
        }
    }

    float bv[8];
#pragma unroll
    for (int j = 0; j < 8; ++j) {
        int nn = (j < 4) ? (tx * 4 + j) : (64 + tx * 4 + (j - 4));
        bv[j] = bias[(nBase + nn) & 511];
    }
#pragma unroll
    for (int i = 0; i < 8; ++i) {
        int mm = (i < 4) ? (ty * 4 + i) : (64 + ty * 4 + (i - 4));
        float* o = g_xg + (size_t)(mBase + mm) * NGATE4 + nBase;
        float4 v0 = make_float4(acc[i][0] + bv[0], acc[i][1] + bv[1],
                                acc[i][2] + bv[2], acc[i][3] + bv[3]);
        float4 v1 = make_float4(acc[i][4] + bv[4], acc[i][5] + bv[5],
                                acc[i][6] + bv[6], acc[i][7] + bv[7]);
        *(float4*)&o[tx * 4]      = v0;
        *(float4*)&o[64 + tx * 4] = v1;
    }
}

// -------- fused kernel: bids 0..127 recurrent, 128..191 producers --------
__global__ __launch_bounds__(256, 1) void lstm_fused_kernel(
    const float* __restrict__ X,
    const float* __restrict__ Wf, const float* __restrict__ bf,
    const float* __restrict__ Wi, const float* __restrict__ bi,
    const float* __restrict__ Wg, const float* __restrict__ bg,
    const float* __restrict__ Wo, const float* __restrict__ bo,
    float* __restrict__ out)
{
    extern __shared__ float smem[];
    const int tid = threadIdx.x;
    const int cb  = blockIdx.x;

    // ================= producer path =================
    if (cb >= N_REC) {
        const int pid = cb - N_REC;
        float* As = smem;          // 2048 floats
        float* Bs = smem + 2048;   // 2048 floats
        for (int j = pid; j < N_JOBS; j += N_PROD) {
            int y = j >> 4;              // m-tile row (2 timesteps)
            int x = j & 15;              // n-tile
            int nBase = x * 128;
            int mBase = y * 128;
            int gate  = nBase >> 9;
            const float* W    = (gate == 0) ? Wf : (gate == 1) ? Wi : (gate == 2) ? Wg : Wo;
            const float* bias = (gate == 0) ? bf : (gate == 1) ? bi : (gate == 2) ? bg : bo;
            __syncthreads();   // protect smem reuse across jobs
            xgemm_job(As, Bs, nBase, mBase, X, W, bias, tid);
            // publish: all threads' g_xg stores ordered via bar.sync, tid0 fences
            __syncthreads();
            if (tid == 0) {
                __threadfence();
                atomicAdd(&g_xgdone[y], 1u);
            }
        }
        return;
    }

    // ================= recurrent path =================
    float* hb = smem;                                  // [2][64*HP]
    float* Ws = smem + 2 * 64 * HP;                    // [16][WS_PITCH] (+16 pad upper half)
    float* gs = Ws + 16 * WS_PITCH + 16;               // [64][GS_PITCH]

    const int u0  = cb * 4;

    // --- load recurrent weight slice (rows r=g*4+j, h-cols [256:768)) ---
    {
        for (int it = 0; it < 8; ++it) {
            int f4 = it * 256 + tid;
            int r  = f4 >> 7;
            int k  = (f4 & 127) * 4;
            int gg = r >> 2, j = r & 3;
            const float* Wp = (gg == 0) ? Wf : (gg == 1) ? Wi : (gg == 2) ? Wg : Wo;
            float4 v = *(const float4*)(Wp + (size_t)(u0 + j) * KDH + DIN + k);
            *(float4*)&Ws[r * WS_PITCH + (r >> 3) * 16 + k] = v;
        }
    }
    __syncthreads();

    const int kp = tid & 15;
    const int rq = (tid >> 4) & 1;
    const int bq = tid >> 5;
    const int eb = tid >> 2;
    const int ej = tid & 3;

    const float* wbase = Ws + (rq * 8) * WS_PITCH + rq * 16 + kp;
    const bool hi0 = (kp & 1);
    const bool hi1 = ((kp >> 1) & 1);
    const bool hi2 = ((kp >> 2) & 1);
    const bool hi3 = ((kp >> 3) & 1);

    float c_reg = 0.0f;
    float h_last = 0.0f;

    for (int t = 0; t < T_STEPS; ++t) {
        // ---- acquire: wait for producer (xg[t]) and step barrier, tid0-only ----
        if (tid == 0) {
            unsigned ytile = (unsigned)t >> 1;
            while (*(volatile unsigned*)&g_xgdone[ytile] < 16u) { }
            if (t > 0) {
                unsigned target = (unsigned)t * 128u;
                while (*(volatile unsigned*)&g_ctr < target) { }
            }
            __threadfence();
        }
        __syncthreads();

        // this step's xg contributions (now guaranteed written)
        const float* xr = g_xg + (size_t)(t * BATCH + eb) * NGATE4 + u0 + ej;
        float xf = xr[0 * HID], xi = xr[1 * HID], xg2 = xr[2 * HID], xo = xr[3 * HID];

        const float* hin = g_h[t & 1];

        // ---- stage chunk 0 ----
        float4 pre[8];
#pragma unroll
        for (int i = 0; i < 8; ++i) {
            int f4 = i * 256 + tid;
            int b  = f4 >> 5;
            int kq = (f4 & 31) * 4;
            pre[i] = *(const float4*)(hin + b * HID + kq);
        }
#pragma unroll
        for (int i = 0; i < 8; ++i) {
            int f4 = i * 256 + tid;
            int b  = f4 >> 5;
            int kq = (f4 & 31) * 4;
            *(float4*)&hb[b * HP + kq] = pre[i];
        }
        __syncthreads();

        float acc[8][8];
#pragma unroll
        for (int i = 0; i < 8; ++i)
#pragma unroll
            for (int j = 0; j < 8; ++j) acc[i][j] = 0.0f;

        // ---- pipelined K-chunk loop (4 chunks of 128) ----
        for (int c = 0; c < 4; ++c) {
            if (c < 3) {
#pragma unroll
                for (int i = 0; i < 8; ++i) {
                    int f4 = i * 256 + tid;
                    int b  = f4 >> 5;
                    int kq = (f4 & 31) * 4;
                    pre[i] = *(const float4*)(hin + b * HID + (c + 1) * 128 + kq);
                }
            }
            const float* hp = hb + (c & 1) * (64 * HP) + (bq * 8) * HP + kp;
            const float* wp = wbase + c * 128;
#pragma unroll
            for (int g8 = 0; g8 < 8; ++g8) {
                float hv[8], wv[8];
#pragma unroll
                for (int jb = 0; jb < 8; ++jb) hv[jb] = hp[jb * HP + g8 * 16];
#pragma unroll
                for (int jr = 0; jr < 8; ++jr) wv[jr] = wp[jr * WS_PITCH + g8 * 16];
#pragma unroll
                for (int jb = 0; jb < 8; ++jb)
#pragma unroll
                    for (int jr = 0; jr < 8; ++jr)
                        acc[jb][jr] = fmaf(hv[jb], wv[jr], acc[jb][jr]);
            }
            if (c < 3) {
                float* b2 = hb + ((c + 1) & 1) * (64 * HP);
#pragma unroll
                for (int i = 0; i < 8; ++i) {
                    int f4 = i * 256 + tid;
                    int b  = f4 >> 5;
                    int kq = (f4 & 31) * 4;
                    *(float4*)&b2[b * HP + kq] = pre[i];
                }
                __syncthreads();
            }
        }

        // ---- value-splitting butterfly over 16 kp lanes ----
        float a2[4][8];
#pragma unroll
        for (int p = 0; p < 4; ++p)
#pragma unroll
            for (int jr = 0; jr < 8; ++jr) {
                float sv = hi0 ? acc[2 * p][jr] : acc[2 * p + 1][jr];
                float kv = hi0 ? acc[2 * p + 1][jr] : acc[2 * p][jr];
                a2[p][jr] = kv + __shfl_xor_sync(0xffffffffu, sv, 1);
            }
        float a3[2][8];
#pragma unroll
        for (int q = 0; q < 2; ++q)
#pragma unroll
            for (int jr = 0; jr < 8; ++jr) {
                float sv = hi1 ? a2[2 * q][jr] : a2[2 * q + 1][jr];
                float kv = hi1 ? a2[2 * q + 1][jr] : a2[2 * q][jr];
                a3[q][jr] = kv + __shfl_xor_sync(0xffffffffu, sv, 2);
            }
        float a4[8];
#pragma unroll
        for (int jr = 0; jr < 8; ++jr) {
            float sv = hi2 ? a3[0][jr] : a3[1][jr];
            float kv = hi2 ? a3[1][jr] : a3[0][jr];
            a4[jr] = kv + __shfl_xor_sync(0xffffffffu, sv, 4);
        }
        float rr[4];
#pragma unroll
        for (int jrr = 0; jrr < 4; ++jrr) {
            float sv = hi3 ? a4[jrr] : a4[jrr + 4];
            float kv = hi3 ? a4[jrr + 4] : a4[jrr];
            rr[jrr] = kv + __shfl_xor_sync(0xffffffffu, sv, 8);
        }
        {
            int row  = bq * 8 + (kp & 7);
            int col0 = rq * 8 + (kp >> 3) * 4;
#pragma unroll
            for (int jrr = 0; jrr < 4; ++jrr)
                gs[row * GS_PITCH + col0 + jrr] = rr[jrr];
        }
        __syncthreads();

        // ---- elementwise LSTM cell ----
        float pf = gs[eb * GS_PITCH + 0  + ej] + xf;
        float pi = gs[eb * GS_PITCH + 4  + ej] + xi;
        float pg = gs[eb * GS_PITCH + 8  + ej] + xg2;
        float po = gs[eb * GS_PITCH + 12 + ej] + xo;
        float fg = fsigm(pf);
        float ig = fsigm(pi);
        float gg = ftanh(pg);
        float og = fsigm(po);
        c_reg = fg * c_reg + ig * gg;
        float hv = og * ftanh(c_reg);
        h_last = hv;

        // critical-path store first
        g_h[(t + 1) & 1][eb * HID + u0 + ej] = hv;

        // ---- release: bar.sync, tid0-only fence + signal ----
        __syncthreads();
        if (tid == 0) {
            __threadfence();
            atomicAdd(&g_ctr, 1u);
        }

        // off-critical-path output write
        out[(size_t)t * (BATCH * HID) + eb * HID + u0 + ej] = hv;
    }

    const size_t off = (size_t)T_STEPS * BATCH * HID;
    out[off + eb * HID + u0 + ej]               = h_last;
    out[off + BATCH * HID + eb * HID + u0 + ej] = c_reg;
}

extern "C" void kernel_launch(void* const* d_in, const int* in_sizes, int n_in,
                              void* d_out, int out_size) {
    const float* X  = (const float*)d_in[0];
    const float* Wf = (const float*)d_in[1];
    const float* bf = (const float*)d_in[2];
    const float* Wi = (const float*)d_in[3];
    const float* bi = (const float*)d_in[4];
    const float* Wg = (const float*)d_in[5];
    const float* bg = (const float*)d_in[6];
    const float* Wo = (const float*)d_in[7];
    const float* bo = (const float*)d_in[8];
    float* out = (float*)d_out;

    const int smem_bytes = (2 * 64 * HP + 16 * WS_PITCH + 16 + 64 * GS_PITCH) * 4;
    cudaFuncSetAttribute(lstm_fused_kernel,
                         cudaFuncAttributeMaxDynamicSharedMemorySize, smem_bytes);

    init_kernel<<<64, 256>>>();
    lstm_fused_kernel<<<N_REC + N_PROD, 256, smem_bytes>>>(
        X, Wf, bf, Wi, bi, Wg, bg, Wo, bo, out);
}

// round 10
// speedup vs baseline: 1.7733x; 1.7733x over previous
#include <cuda_runtime.h>
#include <cuda_bf16.h>
#include <cstdint>
#include <math.h>

#define T_STEPS 512
#define BATCH   64
#define DIN     256
#define HID     512
#define NGATE4  2048   // 4*H
#define KDH     768    // D+H

#define HP       132
#define WS_PITCH 516
#define GS_PITCH 17

// -------- device scratch --------
__device__ float g_xg[(size_t)T_STEPS * BATCH * NGATE4];
__device__ float g_h[2][BATCH * HID];
__device__ unsigned int g_ctr;

// bf16 split operands for tensor xgemm
__device__ __nv_bfloat16 g_xhi[(size_t)T_STEPS * BATCH * DIN];
__device__ __nv_bfloat16 g_xlo[(size_t)T_STEPS * BATCH * DIN];
__device__ __nv_bfloat16 g_whi[(size_t)NGATE4 * DIN];
__device__ __nv_bfloat16 g_wlo[(size_t)NGATE4 * DIN];
__device__ float g_ball[NGATE4];

__device__ __forceinline__ float fsigm(float x) {
    return __fdividef(1.0f, 1.0f + __expf(-x));
}
__device__ __forceinline__ float ftanh(float x) {
    float e = __expf(2.0f * x);
    return 1.0f - __fdividef(2.0f, e + 1.0f);
}

// -------- init --------
__global__ void init_kernel() {
    int idx = blockIdx.x * blockDim.x + threadIdx.x;
    if (idx == 0) g_ctr = 0u;
    int total = 2 * BATCH * HID;
    for (int i = idx; i < total; i += gridDim.x * blockDim.x)
        ((float*)g_h)[i] = 0.0f;
}

// -------- split: fp32 -> bf16 hi/lo; gather W[:, :D] and bias --------
__global__ void split_kernel(
    const float* __restrict__ X,
    const float* __restrict__ Wf, const float* __restrict__ bf,
    const float* __restrict__ Wi, const float* __restrict__ bi,
    const float* __restrict__ Wg, const float* __restrict__ bg,
    const float* __restrict__ Wo, const float* __restrict__ bo)
{
    const int stride = gridDim.x * blockDim.x;
    int idx0 = blockIdx.x * blockDim.x + threadIdx.x;

    const size_t XN = (size_t)T_STEPS * BATCH * DIN;
    for (size_t i = idx0; i < XN; i += stride) {
        float x = X[i];
        __nv_bfloat16 h = __float2bfloat16(x);
        g_xhi[i] = h;
        g_xlo[i] = __float2bfloat16(x - __bfloat162float(h));
    }
    const size_t WN = (size_t)NGATE4 * DIN;
    for (size_t i = idx0; i < WN; i += stride) {
        int r = (int)(i >> 8);
        int k = (int)(i & 255);
        int g = r >> 9, u = r & 511;
        const float* Wp = (g == 0) ? Wf : (g == 1) ? Wi : (g == 2) ? Wg : Wo;
        float w = Wp[(size_t)u * KDH + k];
        __nv_bfloat16 h = __float2bfloat16(w);
        g_whi[i] = h;
        g_wlo[i] = __float2bfloat16(w - __bfloat162float(h));
    }
    for (int r = idx0; r < NGATE4; r += stride) {
        int g = r >> 9, u = r & 511;
        const float* bp = (g == 0) ? bf : (g == 1) ? bi : (g == 2) ? bg : bo;
        g_ball[r] = bp[u];
    }
}

// ---- mma helpers (base-ISA: sm_80+, no 'a' target needed) ----
__device__ __forceinline__ uint32_t smem_u32(const void* p) {
    uint32_t a;
    asm("{ .reg .u64 t; cvta.to.shared.u64 t, %1; cvt.u32.u64 %0, t; }"
        : "=r"(a) : "l"(p));
    return a;
}
__device__ __forceinline__ void ldmx4(uint32_t* r, uint32_t addr) {
    asm volatile("ldmatrix.sync.aligned.m8n8.x4.shared.b16 {%0,%1,%2,%3}, [%4];"
                 : "=r"(r[0]), "=r"(r[1]), "=r"(r[2]), "=r"(r[3]) : "r"(addr));
}
__device__ __forceinline__ void ldmx2(uint32_t* r, uint32_t addr) {
    asm volatile("ldmatrix.sync.aligned.m8n8.x2.shared.b16 {%0,%1}, [%2];"
                 : "=r"(r[0]), "=r"(r[1]) : "r"(addr));
}
__device__ __forceinline__ void mma_bf16(float* d, const uint32_t* a, const uint32_t* b) {
    asm volatile(
        "mma.sync.aligned.m16n8k16.row.col.f32.bf16.bf16.f32 "
        "{%0,%1,%2,%3}, {%4,%5,%6,%7}, {%8,%9}, {%0,%1,%2,%3};"
        : "+f"(d[0]), "+f"(d[1]), "+f"(d[2]), "+f"(d[3])
        : "r"(a[0]), "r"(a[1]), "r"(a[2]), "r"(a[3]), "r"(b[0]), "r"(b[1]));
}

// SMEM byte offsets: 4 chunks of [128 rows][128 B] SW128
#define SM_AHI 0
#define SM_ALO 16384
#define SM_BHI 32768
#define SM_BLO 49152
#define SM_MMA_TOTAL 65536

// -------- xgemm via mma.sync: tile M=128 N=128, K=256 in 4 chunks of 64 -----
__global__ __launch_bounds__(256) void xgemm_mma_kernel()
{
    extern __shared__ char smem[];
    const uint32_t sb = smem_u32(smem);
    const int tid  = threadIdx.x;
    const int lane = tid & 31;
    const int wid  = tid >> 5;
    const int wm   = wid & 1;    // 2 warps over M (64 rows each)
    const int wn   = wid >> 1;   // 4 warps over N (32 cols each)
    const int mBase = blockIdx.y * 128;
    const int nBase = blockIdx.x * 128;

    float acc[4][4][4];
#pragma unroll
    for (int i = 0; i < 4; ++i)
#pragma unroll
        for (int j = 0; j < 4; ++j)
#pragma unroll
            for (int q = 0; q < 4; ++q) acc[i][j][q] = 0.0f;

    // ldmatrix lane-address components
    const int lrow = lane & 7;
    const int lsel = lane >> 3;           // 0..3 (x4); for x2 use lane&8
    const int a_r_off = ((lsel & 1) << 3) + lrow;   // row within 16
    const int a_k_off = (lsel & 2) << 2;            // 0 or 8
    const int b_k_off = (lane & 8);                 // 0 or 8 (x2)

    const int ldRow = tid >> 1;           // gmem load mapping: 2 thr/row
    const int ldQ   = (tid & 1) * 4;      // 4 uint4 each

    for (int c = 0; c < 4; ++c) {
        // ---- stage chunk c: A/B hi+lo, 128 rows x 64 bf16, SW128 ----
        const uint4* pahi = (const uint4*)(g_xhi + (size_t)(mBase + ldRow) * DIN + c * 64);
        const uint4* palo = (const uint4*)(g_xlo + (size_t)(mBase + ldRow) * DIN + c * 64);
        const uint4* pbhi = (const uint4*)(g_whi + (size_t)(nBase + ldRow) * DIN + c * 64);
        const uint4* pblo = (const uint4*)(g_wlo + (size_t)(nBase + ldRow) * DIN + c * 64);
        if (c > 0) __syncthreads();
#pragma unroll
        for (int i = 0; i < 4; ++i) {
            uint32_t off = ldRow * 128 + (ldQ + i) * 16;
            uint32_t sw  = off ^ ((off >> 3) & 0x70);
            *(uint4*)(smem + SM_AHI + sw) = pahi[ldQ + i];
            *(uint4*)(smem + SM_ALO + sw) = palo[ldQ + i];
            *(uint4*)(smem + SM_BHI + sw) = pbhi[ldQ + i];
            *(uint4*)(smem + SM_BLO + sw) = pblo[ldQ + i];
        }
        __syncthreads();

#pragma unroll
        for (int pass = 0; pass < 3; ++pass) {
            const uint32_t abase = sb + ((pass < 2) ? SM_AHI : SM_ALO);
            const uint32_t bbase = sb + ((pass == 1) ? SM_BLO : SM_BHI);
#pragma unroll
            for (int k16 = 0; k16 < 4; ++k16) {
                uint32_t afr[4][4];
#pragma unroll
                for (int mf = 0; mf < 4; ++mf) {
                    int r  = wm * 64 + mf * 16 + a_r_off;
                    int kk = k16 * 16 + a_k_off;
                    uint32_t off = r * 128 + kk * 2;
                    off ^= (off >> 3) & 0x70;
                    ldmx4(afr[mf], abase + off);
                }
                uint32_t bfr[4][2];
#pragma unroll
                for (int nf = 0; nf < 4; ++nf) {
                    int r  = wn * 32 + nf * 8 + lrow;
                    int kk = k16 * 16 + b_k_off;
                    uint32_t off = r * 128 + kk * 2;
                    off ^= (off >> 3) & 0x70;
                    ldmx2(bfr[nf], bbase + off);
                }
#pragma unroll
                for (int mf = 0; mf < 4; ++mf)
#pragma unroll
                    for (int nf = 0; nf < 4; ++nf)
                        mma_bf16(acc[mf][nf], afr[mf], bfr[nf]);
            }
        }
    }

    // ---- epilogue: direct stores (8B each), add bias ----
#pragma unroll
    for (int nf = 0; nf < 4; ++nf) {
        int n = nBase + wn * 32 + nf * 8 + (lane & 3) * 2;
        float b0 = g_ball[n], b1 = g_ball[n + 1];
#pragma unroll
        for (int mf = 0; mf < 4; ++mf) {
            int r0 = mBase + wm * 64 + mf * 16 + (lane >> 2);
            float2 v0 = make_float2(acc[mf][nf][0] + b0, acc[mf][nf][1] + b1);
            float2 v1 = make_float2(acc[mf][nf][2] + b0, acc[mf][nf][3] + b1);
            *(float2*)&g_xg[(size_t)r0 * NGATE4 + n]       = v0;
            *(float2*)&g_xg[(size_t)(r0 + 8) * NGATE4 + n] = v1;
        }
    }
}

// -------- kernel 2: persistent recurrent loop (R6, unchanged) --------
__global__ __launch_bounds__(256, 1) void lstm_rec_kernel(
    const float* __restrict__ Wf, const float* __restrict__ Wi,
    const float* __restrict__ Wg, const float* __restrict__ Wo,
    float* __restrict__ out)
{
    extern __shared__ float smemf[];
    float* hb = smemf;
    float* Ws = smemf + 2 * 64 * HP;
    float* gs = Ws + 16 * WS_PITCH + 16;

    const int tid = threadIdx.x;
    const int cb  = blockIdx.x;
    const int u0  = cb * 4;

    {
        for (int it = 0; it < 8; ++it) {
            int f4 = it * 256 + tid;
            int r  = f4 >> 7;
            int k  = (f4 & 127) * 4;
            int gg = r >> 2, j = r & 3;
            const float* Wp = (gg == 0) ? Wf : (gg == 1) ? Wi : (gg == 2) ? Wg : Wo;
            float4 v = *(const float4*)(Wp + (size_t)(u0 + j) * KDH + DIN + k);
            *(float4*)&Ws[r * WS_PITCH + (r >> 3) * 16 + k] = v;
        }
    }
    __syncthreads();

    const int kp = tid & 15;
    const int rq = (tid >> 4) & 1;
    const int bq = tid >> 5;
    const int eb = tid >> 2;
    const int ej = tid & 3;

    const float* wbase = Ws + (rq * 8) * WS_PITCH + rq * 16 + kp;
    const bool hi0 = (kp & 1);
    const bool hi1 = ((kp >> 1) & 1);
    const bool hi2 = ((kp >> 2) & 1);
    const bool hi3 = ((kp >> 3) & 1);

    float c_reg = 0.0f;
    float h_last = 0.0f;

    for (int t = 0; t < T_STEPS; ++t) {
        const float* xr = g_xg + (size_t)(t * BATCH + eb) * NGATE4 + u0 + ej;
        float xf = xr[0 * HID], xi = xr[1 * HID], xg2 = xr[2 * HID], xo = xr[3 * HID];

        if (t > 0) {
            if (tid == 0) {
                unsigned target = (unsigned)t * 128u;
                while (*(volatile unsigned*)&g_ctr < target) { }
                __threadfence();
            }
            __syncthreads();
        }

        const float* hin = g_h[t & 1];

        float4 pre[8];
#pragma unroll
        for (int i = 0; i < 8; ++i) {
            int f4 = i * 256 + tid;
            int b  = f4 >> 5;
            int kq = (f4 & 31) * 4;
            pre[i] = *(const float4*)(hin + b * HID + kq);
        }
#pragma unroll
        for (int i = 0; i < 8; ++i) {
            int f4 = i * 256 + tid;
            int b  = f4 >> 5;
            int kq = (f4 & 31) * 4;
            *(float4*)&hb[b * HP + kq] = pre[i];
        }
        __syncthreads();

        float acc[8][8];
#pragma unroll
        for (int i = 0; i < 8; ++i)
#pragma unroll
            for (int j = 0; j < 8; ++j) acc[i][j] = 0.0f;

        for (int c = 0; c < 4; ++c) {
            if (c < 3) {
#pragma unroll
                for (int i = 0; i < 8; ++i) {
                    int f4 = i * 256 + tid;
                    int b  = f4 >> 5;
                    int kq = (f4 & 31) * 4;
                    pre[i] = *(const float4*)(hin + b * HID + (c + 1) * 128 + kq);
                }
            }
            const float* hp = hb + (c & 1) * (64 * HP) + (bq * 8) * HP + kp;
            const float* wp = wbase + c * 128;
#pragma unroll
            for (int g8 = 0; g8 < 8; ++g8) {
                float hv[8], wv[8];
#pragma unroll
                for (int jb = 0; jb < 8; ++jb) hv[jb] = hp[jb * HP + g8 * 16];
#pragma unroll
                for (int jr = 0; jr < 8; ++jr) wv[jr] = wp[jr * WS_PITCH + g8 * 16];
#pragma unroll
                for (int jb = 0; jb < 8; ++jb)
#pragma unroll
                    for (int jr = 0; jr < 8; ++jr)
                        acc[jb][jr] = fmaf(hv[jb], wv[jr], acc[jb][jr]);
            }
            if (c < 3) {
                float* b2 = hb + ((c + 1) & 1) * (64 * HP);
#pragma unroll
                for (int i = 0; i < 8; ++i) {
                    int f4 = i * 256 + tid;
                    int b  = f4 >> 5;
                    int kq = (f4 & 31) * 4;
                    *(float4*)&b2[b * HP + kq] = pre[i];
                }
                __syncthreads();
            }
        }

        float a2[4][8];
#pragma unroll
        for (int p = 0; p < 4; ++p)
#pragma unroll
            for (int jr = 0; jr < 8; ++jr) {
                float sv = hi0 ? acc[2 * p][jr] : acc[2 * p + 1][jr];
                float kv = hi0 ? acc[2 * p + 1][jr] : acc[2 * p][jr];
                a2[p][jr] = kv + __shfl_xor_sync(0xffffffffu, sv, 1);
            }
        float a3[2][8];
#pragma unroll
        for (int q = 0; q < 2; ++q)
#pragma unroll
            for (int jr = 0; jr < 8; ++jr) {
                float sv = hi1 ? a2[2 * q][jr] : a2[2 * q + 1][jr];
                float kv = hi1 ? a2[2 * q + 1][jr] : a2[2 * q][jr];
                a3[q][jr] = kv + __shfl_xor_sync(0xffffffffu, sv, 2);
            }
        float a4[8];
#pragma unroll
        for (int jr = 0; jr < 8; ++jr) {
            float sv = hi2 ? a3[0][jr] : a3[1][jr];
            float kv = hi2 ? a3[1][jr] : a3[0][jr];
            a4[jr] = kv + __shfl_xor_sync(0xffffffffu, sv, 4);
        }
        float rr[4];
#pragma unroll
        for (int jrr = 0; jrr < 4; ++jrr) {
            float sv = hi3 ? a4[jrr] : a4[jrr + 4];
            float kv = hi3 ? a4[jrr + 4] : a4[jrr];
            rr[jrr] = kv + __shfl_xor_sync(0xffffffffu, sv, 8);
        }
        {
            int row  = bq * 8 + (kp & 7);
            int col0 = rq * 8 + (kp >> 3) * 4;
#pragma unroll
            for (int jrr = 0; jrr < 4; ++jrr)
                gs[row * GS_PITCH + col0 + jrr] = rr[jrr];
        }
        __syncthreads();

        float pf = gs[eb * GS_PITCH + 0  + ej] + xf;
        float pi = gs[eb * GS_PITCH + 4  + ej] + xi;
        float pg = gs[eb * GS_PITCH + 8  + ej] + xg2;
        float po = gs[eb * GS_PITCH + 12 + ej] + xo;
        float fg = fsigm(pf);
        float ig = fsigm(pi);
        float gg = ftanh(pg);
        float og = fsigm(po);
        c_reg = fg * c_reg + ig * gg;
        float hv = og * ftanh(c_reg);
        h_last = hv;

        g_h[(t + 1) & 1][eb * HID + u0 + ej] = hv;

        __syncthreads();
        if (tid == 0) {
            __threadfence();
            atomicAdd(&g_ctr, 1u);
        }

        out[(size_t)t * (BATCH * HID) + eb * HID + u0 + ej] = hv;
    }

    const size_t off = (size_t)T_STEPS * BATCH * HID;
    out[off + eb * HID + u0 + ej]               = h_last;
    out[off + BATCH * HID + eb * HID + u0 + ej] = c_reg;
}

extern "C" void kernel_launch(void* const* d_in, const int* in_sizes, int n_in,
                              void* d_out, int out_size) {
    const float* X  = (const float*)d_in[0];
    const float* Wf = (const float*)d_in[1];
    const float* bf = (const float*)d_in[2];
    const float* Wi = (const float*)d_in[3];
    const float* bi = (const float*)d_in[4];
    const float* Wg = (const float*)d_in[5];
    const float* bg = (const float*)d_in[6];
    const float* Wo = (const float*)d_in[7];
    const float* bo = (const float*)d_in[8];
    float* out = (float*)d_out;

    const int smem_rec = (2 * 64 * HP + 16 * WS_PITCH + 16 + 64 * GS_PITCH) * 4;
    cudaFuncSetAttribute(lstm_rec_kernel,
                         cudaFuncAttributeMaxDynamicSharedMemorySize, smem_rec);
    cudaFuncSetAttribute(xgemm_mma_kernel,
                         cudaFuncAttributeMaxDynamicSharedMemorySize, SM_MMA_TOTAL);

    init_kernel<<<64, 256>>>();
    split_kernel<<<1024, 256>>>(X, Wf, bf, Wi, bi, Wg, bg, Wo, bo);
    xgemm_mma_kernel<<<dim3(16, 256), 256, SM_MMA_TOTAL>>>();
    lstm_rec_kernel<<<128, 256, smem_rec>>>(Wf, Wi, Wg, Wo, out);
}

// round 11
// speedup vs baseline: 1.8604x; 1.0491x over previous
#include <cuda_runtime.h>
#include <cuda_bf16.h>
#include <cstdint>
#include <math.h>

#define T_STEPS 512
#define BATCH   64
#define DIN     256
#define HID     512
#define NGATE4  2048   // 4*H
#define KDH     768    // D+H
#define GSP     18     // gate smem pitch (even -> aligned float2)

// -------- device scratch --------
__device__ float g_xg[(size_t)T_STEPS * BATCH * NGATE4];
__device__ unsigned int g_ctr;

// h state as bf16 hi/lo planes, ping-pong
__device__ __nv_bfloat16 g_hbhi[2][BATCH * HID];
__device__ __nv_bfloat16 g_hblo[2][BATCH * HID];

// bf16 split operands for tensor xgemm
__device__ __nv_bfloat16 g_xhi[(size_t)T_STEPS * BATCH * DIN];
__device__ __nv_bfloat16 g_xlo[(size_t)T_STEPS * BATCH * DIN];
__device__ __nv_bfloat16 g_whi[(size_t)NGATE4 * DIN];
__device__ __nv_bfloat16 g_wlo[(size_t)NGATE4 * DIN];
__device__ float g_ball[NGATE4];

__device__ __forceinline__ float fsigm(float x) {
    return __fdividef(1.0f, 1.0f + __expf(-x));
}
__device__ __forceinline__ float ftanh(float x) {
    float e = __expf(2.0f * x);
    return 1.0f - __fdividef(2.0f, e + 1.0f);
}

// -------- init: barrier + h0 planes --------
__global__ void init_kernel() {
    int idx = blockIdx.x * blockDim.x + threadIdx.x;
    if (idx == 0) g_ctr = 0u;
    int total = BATCH * HID;
    for (int i = idx; i < total; i += gridDim.x * blockDim.x) {
        g_hbhi[0][i] = __float2bfloat16(0.0f);
        g_hblo[0][i] = __float2bfloat16(0.0f);
    }
}

// -------- split: fp32 -> bf16 hi/lo for X and W[:, :D]; gather bias --------
__global__ void split_kernel(
    const float* __restrict__ X,
    const float* __restrict__ Wf, const float* __restrict__ bf,
    const float* __restrict__ Wi, const float* __restrict__ bi,
    const float* __restrict__ Wg, const float* __restrict__ bg,
    const float* __restrict__ Wo, const float* __restrict__ bo)
{
    const int stride = gridDim.x * blockDim.x;
    int idx0 = blockIdx.x * blockDim.x + threadIdx.x;

    const size_t XN = (size_t)T_STEPS * BATCH * DIN;
    for (size_t i = idx0; i < XN; i += stride) {
        float x = X[i];
        __nv_bfloat16 h = __float2bfloat16(x);
        g_xhi[i] = h;
        g_xlo[i] = __float2bfloat16(x - __bfloat162float(h));
    }
    const size_t WN = (size_t)NGATE4 * DIN;
    for (size_t i = idx0; i < WN; i += stride) {
        int r = (int)(i >> 8);
        int k = (int)(i & 255);
        int g = r >> 9, u = r & 511;
        const float* Wp = (g == 0) ? Wf : (g == 1) ? Wi : (g == 2) ? Wg : Wo;
        float w = Wp[(size_t)u * KDH + k];
        __nv_bfloat16 h = __float2bfloat16(w);
        g_whi[i] = h;
        g_wlo[i] = __float2bfloat16(w - __bfloat162float(h));
    }
    for (int r = idx0; r < NGATE4; r += stride) {
        int g = r >> 9, u = r & 511;
        const float* bp = (g == 0) ? bf : (g == 1) ? bi : (g == 2) ? bg : bo;
        g_ball[r] = bp[u];
    }
}

// ---- mma helpers (base ISA, compiles for compute_103) ----
__device__ __forceinline__ uint32_t smem_u32(const void* p) {
    uint32_t a;
    asm("{ .reg .u64 t; cvta.to.shared.u64 t, %1; cvt.u32.u64 %0, t; }"
        : "=r"(a) : "l"(p));
    return a;
}
__device__ __forceinline__ void ldmx4(uint32_t* r, uint32_t addr) {
    asm volatile("ldmatrix.sync.aligned.m8n8.x4.shared.b16 {%0,%1,%2,%3}, [%4];"
                 : "=r"(r[0]), "=r"(r[1]), "=r"(r[2]), "=r"(r[3]) : "r"(addr));
}
__device__ __forceinline__ void ldmx2(uint32_t* r, uint32_t addr) {
    asm volatile("ldmatrix.sync.aligned.m8n8.x2.shared.b16 {%0,%1}, [%2];"
                 : "=r"(r[0]), "=r"(r[1]) : "r"(addr));
}
__device__ __forceinline__ void mma_bf16(float* d, const uint32_t* a, const uint32_t* b) {
    asm volatile(
        "mma.sync.aligned.m16n8k16.row.col.f32.bf16.bf16.f32 "
        "{%0,%1,%2,%3}, {%4,%5,%6,%7}, {%8,%9}, {%0,%1,%2,%3};"
        : "+f"(d[0]), "+f"(d[1]), "+f"(d[2]), "+f"(d[3])
        : "r"(a[0]), "r"(a[1]), "r"(a[2]), "r"(a[3]), "r"(b[0]), "r"(b[1]));
}

// ======================= xgemm (R10, validated) =======================
#define SM_AHI 0
#define SM_ALO 16384
#define SM_BHI 32768
#define SM_BLO 49152
#define SM_MMA_TOTAL 65536

__global__ __launch_bounds__(256) void xgemm_mma_kernel()
{
    extern __shared__ char smem[];
    const uint32_t sb = smem_u32(smem);
    const int tid  = threadIdx.x;
    const int lane = tid & 31;
    const int wid  = tid >> 5;
    const int wm   = wid & 1;
    const int wn   = wid >> 1;
    const int mBase = blockIdx.y * 128;
    const int nBase = blockIdx.x * 128;

    float acc[4][4][4];
#pragma unroll
    for (int i = 0; i < 4; ++i)
#pragma unroll
        for (int j = 0; j < 4; ++j)
#pragma unroll
            for (int q = 0; q < 4; ++q) acc[i][j][q] = 0.0f;

    const int lrow = lane & 7;
    const int lsel = lane >> 3;
    const int a_r_off = ((lsel & 1) << 3) + lrow;
    const int a_k_off = (lsel & 2) << 2;
    const int b_k_off = (lane & 8);

    const int ldRow = tid >> 1;
    const int ldQ   = (tid & 1) * 4;

    for (int c = 0; c < 4; ++c) {
        const uint4* pahi = (const uint4*)(g_xhi + (size_t)(mBase + ldRow) * DIN + c * 64);
        const uint4* palo = (const uint4*)(g_xlo + (size_t)(mBase + ldRow) * DIN + c * 64);
        const uint4* pbhi = (const uint4*)(g_whi + (size_t)(nBase + ldRow) * DIN + c * 64);
        const uint4* pblo = (const uint4*)(g_wlo + (size_t)(nBase + ldRow) * DIN + c * 64);
        if (c > 0) __syncthreads();
#pragma unroll
        for (int i = 0; i < 4; ++i) {
            uint32_t off = ldRow * 128 + (ldQ + i) * 16;
            uint32_t sw  = off ^ ((off >> 3) & 0x70);
            *(uint4*)(smem + SM_AHI + sw) = pahi[ldQ + i];
            *(uint4*)(smem + SM_ALO + sw) = palo[ldQ + i];
            *(uint4*)(smem + SM_BHI + sw) = pbhi[ldQ + i];
            *(uint4*)(smem + SM_BLO + sw) = pblo[ldQ + i];
        }
        __syncthreads();

#pragma unroll
        for (int pass = 0; pass < 3; ++pass) {
            const uint32_t abase = sb + ((pass < 2) ? SM_AHI : SM_ALO);
            const uint32_t bbase = sb + ((pass == 1) ? SM_BLO : SM_BHI);
#pragma unroll
            for (int k16 = 0; k16 < 4; ++k16) {
                uint32_t afr[4][4];
#pragma unroll
                for (int mf = 0; mf < 4; ++mf) {
                    int r  = wm * 64 + mf * 16 + a_r_off;
                    int kk = k16 * 16 + a_k_off;
                    uint32_t off = r * 128 + kk * 2;
                    off ^= (off >> 3) & 0x70;
                    ldmx4(afr[mf], abase + off);
                }
                uint32_t bfr[4][2];
#pragma unroll
                for (int nf = 0; nf < 4; ++nf) {
                    int r  = wn * 32 + nf * 8 + lrow;
                    int kk = k16 * 16 + b_k_off;
                    uint32_t off = r * 128 + kk * 2;
                    off ^= (off >> 3) & 0x70;
                    ldmx2(bfr[nf], bbase + off);
                }
#pragma unroll
                for (int mf = 0; mf < 4; ++mf)
#pragma unroll
                    for (int nf = 0; nf < 4; ++nf)
                        mma_bf16(acc[mf][nf], afr[mf], bfr[nf]);
            }
        }
    }

#pragma unroll
    for (int nf = 0; nf < 4; ++nf) {
        int n = nBase + wn * 32 + nf * 8 + (lane & 3) * 2;
        float b0 = g_ball[n], b1 = g_ball[n + 1];
#pragma unroll
        for (int mf = 0; mf < 4; ++mf) {
            int r0 = mBase + wm * 64 + mf * 16 + (lane >> 2);
            float2 v0 = make_float2(acc[mf][nf][0] + b0, acc[mf][nf][1] + b1);
            float2 v1 = make_float2(acc[mf][nf][2] + b0, acc[mf][nf][3] + b1);
            *(float2*)&g_xg[(size_t)r0 * NGATE4 + n]       = v0;
            *(float2*)&g_xg[(size_t)(r0 + 8) * NGATE4 + n] = v1;
        }
    }
}

// ======================= recurrent kernel: HMMA ========================
// smem layout (bytes): h-hi 8 chunks x [64 rows x 128B] = 64KB; h-lo 64KB;
// W-hi 8 x [16 x 128B] = 16KB; W-lo 16KB; gs [64][GSP] f32.
#define HS_HI 0
#define HS_LO 65536
#define WS_HI 131072
#define WS_LO 147456
#define GS_OFF 163840
#define SM_REC_TOTAL (GS_OFF + 64 * GSP * 4)

__global__ __launch_bounds__(256, 1) void lstm_rec_mma_kernel(
    const float* __restrict__ Wf, const float* __restrict__ Wi,
    const float* __restrict__ Wg, const float* __restrict__ Wo,
    float* __restrict__ out)
{
    extern __shared__ char sm[];
    const uint32_t sb = smem_u32(sm);
    float* gs = (float*)(sm + GS_OFF);

    const int tid  = threadIdx.x;
    const int lane = tid & 31;
    const int wid  = tid >> 5;
    const int wm   = wid & 3;      // 4 warps over batch (16 rows each)
    const int wn   = wid >> 2;     // 2 warps over gate rows (8 each)
    const int cb   = blockIdx.x;
    const int u0   = cb * 4;

    // --- prologue: load + split W recurrent slice into SW128 chunks ---
    for (int it = 0; it < 32; ++it) {
        int idx = it * 256 + tid;          // 0..8191
        int r = idx >> 9;                  // 0..15
        int k = idx & 511;
        int g = r >> 2, j = r & 3;
        const float* Wp = (g == 0) ? Wf : (g == 1) ? Wi : (g == 2) ? Wg : Wo;
        float w = Wp[(size_t)(u0 + j) * KDH + DIN + k];
        __nv_bfloat16 whi = __float2bfloat16(w);
        __nv_bfloat16 wlo = __float2bfloat16(w - __bfloat162float(whi));
        uint32_t off = r * 128 + (k & 63) * 2;
        off ^= (off >> 3) & 0x70;
        off += (k >> 6) * 2048;
        *(__nv_bfloat16*)(sm + WS_HI + off) = whi;
        *(__nv_bfloat16*)(sm + WS_LO + off) = wlo;
    }
    __syncthreads();

    // --- preload B fragments (weights constant all steps) ---
    const int lrow = lane & 7;
    const int lsel = lane >> 3;
    uint32_t bhi[32][2], blo[32][2];
#pragma unroll
    for (int kk = 0; kk < 32; ++kk) {
        uint32_t off = (wn * 8 + lrow) * 128 + ((kk & 3) * 16 + (lane & 8)) * 2;
        off ^= (off >> 3) & 0x70;
        uint32_t base = (kk >> 2) * 2048 + off;
        ldmx2(bhi[kk], sb + WS_HI + base);
        ldmx2(blo[kk], sb + WS_LO + base);
    }

    const int a_r = wm * 16 + ((lsel & 1) << 3) + lrow;
    const int a_k = (lsel & 2) << 2;

    const int eb = tid >> 2;
    const int ej = tid & 3;

    // staging geometry: per chunk, thread covers 2 consecutive 16B units
    const int sv = tid * 2;
    const int sr = sv >> 3;        // row 0..63
    const int su = sv & 7;         // unit 0..6 (even)
    uint32_t so0 = sr * 128 + su * 16;       so0 ^= (so0 >> 3) & 0x70;
    uint32_t so1 = sr * 128 + (su + 1) * 16; so1 ^= (so1 >> 3) & 0x70;

    float c_reg = 0.0f;
    float h_last = 0.0f;

    for (int t = 0; t < T_STEPS; ++t) {
        // prefetch xg (independent of barrier)
        const float* xr = g_xg + (size_t)(t * BATCH + eb) * NGATE4 + u0 + ej;
        float xf = xr[0 * HID], xi = xr[1 * HID], xg2 = xr[2 * HID], xo = xr[3 * HID];

        // ---- acquire ----
        if (t > 0) {
            if (tid == 0) {
                unsigned target = (unsigned)t * 128u;
                while (*(volatile unsigned*)&g_ctr < target) { }
                __threadfence();
            }
            __syncthreads();
        }

        const __nv_bfloat16* hhi = g_hbhi[t & 1];
        const __nv_bfloat16* hlo = g_hblo[t & 1];

        // ---- stage chunk 0 ----
        uint4 pre[4];
        {
            const uint4* s1 = (const uint4*)(hhi + sr * HID + su * 8);
            const uint4* s2 = (const uint4*)(hlo + sr * HID + su * 8);
            pre[0] = s1[0]; pre[1] = s1[1]; pre[2] = s2[0]; pre[3] = s2[1];
            *(uint4*)(sm + HS_HI + so0) = pre[0];
            *(uint4*)(sm + HS_HI + so1) = pre[1];
            *(uint4*)(sm + HS_LO + so0) = pre[2];
            *(uint4*)(sm + HS_LO + so1) = pre[3];
        }
        __syncthreads();

        float c4[4] = {0.f, 0.f, 0.f, 0.f};

        // ---- pipelined chunk loop ----
#pragma unroll
        for (int c = 0; c < 8; ++c) {
            if (c < 7) {
                const uint4* s1 = (const uint4*)(hhi + sr * HID + (c + 1) * 64 + su * 8);
                const uint4* s2 = (const uint4*)(hlo + sr * HID + (c + 1) * 64 + su * 8);
                pre[0] = s1[0]; pre[1] = s1[1]; pre[2] = s2[0]; pre[3] = s2[1];
            }
#pragma unroll
            for (int q = 0; q < 4; ++q) {
                const int kk = c * 4 + q;
                uint32_t off = a_r * 128 + (q * 16 + a_k) * 2;
                off ^= (off >> 3) & 0x70;
                uint32_t ahi4[4], alo4[4];
                ldmx4(ahi4, sb + HS_HI + c * 8192 + off);
                ldmx4(alo4, sb + HS_LO + c * 8192 + off);
                mma_bf16(c4, ahi4, bhi[kk]);
                mma_bf16(c4, ahi4, blo[kk]);
                mma_bf16(c4, alo4, bhi[kk]);
                mma_bf16(c4, alo4, blo[kk]);
            }
            if (c < 7) {
                *(uint4*)(sm + HS_HI + (c + 1) * 8192 + so0) = pre[0];
                *(uint4*)(sm + HS_HI + (c + 1) * 8192 + so1) = pre[1];
                *(uint4*)(sm + HS_LO + (c + 1) * 8192 + so0) = pre[2];
                *(uint4*)(sm + HS_LO + (c + 1) * 8192 + so1) = pre[3];
                __syncthreads();
            }
        }

        // ---- epilogue: fragments -> gs ----
        {
            int row = wm * 16 + (lane >> 2);
            int col = wn * 8 + (lane & 3) * 2;
            *(float2*)&gs[row * GSP + col]       = make_float2(c4[0], c4[1]);
            *(float2*)&gs[(row + 8) * GSP + col] = make_float2(c4[2], c4[3]);
        }
        __syncthreads();

        // ---- elementwise LSTM cell for (eb, u0+ej) ----
        float pf = gs[eb * GSP + 0  + ej] + xf;
        float pi = gs[eb * GSP + 4  + ej] + xi;
        float pg = gs[eb * GSP + 8  + ej] + xg2;
        float po = gs[eb * GSP + 12 + ej] + xo;
        float fg = fsigm(pf);
        float ig = fsigm(pi);
        float gg = ftanh(pg);
        float og = fsigm(po);
        c_reg = fg * c_reg + ig * gg;
        float hv = og * ftanh(c_reg);
        h_last = hv;

        // critical-path: h bf16 hi/lo planes
        __nv_bfloat16 hb = __float2bfloat16(hv);
        __nv_bfloat16 lb = __float2bfloat16(hv - __bfloat162float(hb));
        g_hbhi[(t + 1) & 1][eb * HID + u0 + ej] = hb;
        g_hblo[(t + 1) & 1][eb * HID + u0 + ej] = lb;

        // ---- release ----
        __syncthreads();
        if (tid == 0) {
            __threadfence();
            atomicAdd(&g_ctr, 1u);
        }

        out[(size_t)t * (BATCH * HID) + eb * HID + u0 + ej] = hv;
    }

    const size_t off = (size_t)T_STEPS * BATCH * HID;
    out[off + eb * HID + u0 + ej]               = h_last;
    out[off + BATCH * HID + eb * HID + u0 + ej] = c_reg;
}

extern "C" void kernel_launch(void* const* d_in, const int* in_sizes, int n_in,
                              void* d_out, int out_size) {
    const float* X  = (const float*)d_in[0];
    const float* Wf = (const float*)d_in[1];
    const float* bf = (const float*)d_in[2];
    const float* Wi = (const float*)d_in[3];
    const float* bi = (const float*)d_in[4];
    const float* Wg = (const float*)d_in[5];
    const float* bg = (const float*)d_in[6];
    const float* Wo = (const float*)d_in[7];
    const float* bo = (const float*)d_in[8];
    float* out = (float*)d_out;

    cudaFuncSetAttribute(xgemm_mma_kernel,
                         cudaFuncAttributeMaxDynamicSharedMemorySize, SM_MMA_TOTAL);
    cudaFuncSetAttribute(lstm_rec_mma_kernel,
                         cudaFuncAttributeMaxDynamicSharedMemorySize, SM_REC_TOTAL);

    init_kernel<<<64, 256>>>();
    split_kernel<<<1024, 256>>>(X, Wf, bf, Wi, bi, Wg, bg, Wo, bo);
    xgemm_mma_kernel<<<dim3(16, 256), 256, SM_MMA_TOTAL>>>();
    lstm_rec_mma_kernel<<<128, 256, SM_REC_TOTAL>>>(Wf, Wi, Wg, Wo, out);
}

// round 12
// speedup vs baseline: 2.6696x; 1.4350x over previous
#include <cuda_runtime.h>
#include <cuda_bf16.h>
#include <cstdint>
#include <math.h>

#define T_STEPS 512
#define BATCH   64
#define DIN     256
#define HID     512
#define NGATE4  2048   // 4*H
#define KDH     768    // D+H
#define GSP     18     // gate smem pitch

// -------- device scratch --------
__device__ float g_xg[(size_t)T_STEPS * BATCH * NGATE4];
__device__ unsigned int g_ctr;

// h state as bf16 hi/lo planes, ping-pong
__device__ __nv_bfloat16 g_hbhi[2][BATCH * HID];
__device__ __nv_bfloat16 g_hblo[2][BATCH * HID];

// bf16 split operands for tensor xgemm
__device__ __nv_bfloat16 g_xhi[(size_t)T_STEPS * BATCH * DIN];
__device__ __nv_bfloat16 g_xlo[(size_t)T_STEPS * BATCH * DIN];
__device__ __nv_bfloat16 g_whi[(size_t)NGATE4 * DIN];
__device__ __nv_bfloat16 g_wlo[(size_t)NGATE4 * DIN];
__device__ float g_ball[NGATE4];

__device__ __forceinline__ float fsigm(float x) {
    return __fdividef(1.0f, 1.0f + __expf(-x));
}
__device__ __forceinline__ float ftanh(float x) {
    float e = __expf(2.0f * x);
    return 1.0f - __fdividef(2.0f, e + 1.0f);
}

// -------- init --------
__global__ void init_kernel() {
    int idx = blockIdx.x * blockDim.x + threadIdx.x;
    if (idx == 0) g_ctr = 0u;
    int total = BATCH * HID;
    for (int i = idx; i < total; i += gridDim.x * blockDim.x) {
        g_hbhi[0][i] = __float2bfloat16(0.0f);
        g_hblo[0][i] = __float2bfloat16(0.0f);
    }
}

// -------- split --------
__global__ void split_kernel(
    const float* __restrict__ X,
    const float* __restrict__ Wf, const float* __restrict__ bf,
    const float* __restrict__ Wi, const float* __restrict__ bi,
    const float* __restrict__ Wg, const float* __restrict__ bg,
    const float* __restrict__ Wo, const float* __restrict__ bo)
{
    const int stride = gridDim.x * blockDim.x;
    int idx0 = blockIdx.x * blockDim.x + threadIdx.x;

    const size_t XN = (size_t)T_STEPS * BATCH * DIN;
    for (size_t i = idx0; i < XN; i += stride) {
        float x = X[i];
        __nv_bfloat16 h = __float2bfloat16(x);
        g_xhi[i] = h;
        g_xlo[i] = __float2bfloat16(x - __bfloat162float(h));
    }
    const size_t WN = (size_t)NGATE4 * DIN;
    for (size_t i = idx0; i < WN; i += stride) {
        int r = (int)(i >> 8);
        int k = (int)(i & 255);
        int g = r >> 9, u = r & 511;
        const float* Wp = (g == 0) ? Wf : (g == 1) ? Wi : (g == 2) ? Wg : Wo;
        float w = Wp[(size_t)u * KDH + k];
        __nv_bfloat16 h = __float2bfloat16(w);
        g_whi[i] = h;
        g_wlo[i] = __float2bfloat16(w - __bfloat162float(h));
    }
    for (int r = idx0; r < NGATE4; r += stride) {
        int g = r >> 9, u = r & 511;
        const float* bp = (g == 0) ? bf : (g == 1) ? bi : (g == 2) ? bg : bo;
        g_ball[r] = bp[u];
    }
}

// ---- mma / async helpers (base ISA) ----
__device__ __forceinline__ uint32_t smem_u32(const void* p) {
    uint32_t a;
    asm("{ .reg .u64 t; cvta.to.shared.u64 t, %1; cvt.u32.u64 %0, t; }"
        : "=r"(a) : "l"(p));
    return a;
}
__device__ __forceinline__ void ldmx4(uint32_t* r, uint32_t addr) {
    asm volatile("ldmatrix.sync.aligned.m8n8.x4.shared.b16 {%0,%1,%2,%3}, [%4];"
                 : "=r"(r[0]), "=r"(r[1]), "=r"(r[2]), "=r"(r[3]) : "r"(addr));
}
__device__ __forceinline__ void ldmx2(uint32_t* r, uint32_t addr) {
    asm volatile("ldmatrix.sync.aligned.m8n8.x2.shared.b16 {%0,%1}, [%2];"
                 : "=r"(r[0]), "=r"(r[1]) : "r"(addr));
}
__device__ __forceinline__ void mma_bf16(float* d, const uint32_t* a, const uint32_t* b) {
    asm volatile(
        "mma.sync.aligned.m16n8k16.row.col.f32.bf16.bf16.f32 "
        "{%0,%1,%2,%3}, {%4,%5,%6,%7}, {%8,%9}, {%0,%1,%2,%3};"
        : "+f"(d[0]), "+f"(d[1]), "+f"(d[2]), "+f"(d[3])
        : "r"(a[0]), "r"(a[1]), "r"(a[2]), "r"(a[3]), "r"(b[0]), "r"(b[1]));
}
__device__ __forceinline__ void cp16(uint32_t dst, const void* src) {
    asm volatile("cp.async.cg.shared.global [%0], [%1], 16;"
                 :: "r"(dst), "l"(src) : "memory");
}
__device__ __forceinline__ void cp_wait_all() {
    asm volatile("cp.async.commit_group;\n\tcp.async.wait_group 0;" ::: "memory");
}

// ======================= xgemm (R10, validated) =======================
#define SM_AHI 0
#define SM_ALO 16384
#define SM_BHI 32768
#define SM_BLO 49152
#define SM_MMA_TOTAL 65536

__global__ __launch_bounds__(256) void xgemm_mma_kernel()
{
    extern __shared__ char smem[];
    const uint32_t sb = smem_u32(smem);
    const int tid  = threadIdx.x;
    const int lane = tid & 31;
    const int wid  = tid >> 5;
    const int wm   = wid & 1;
    const int wn   = wid >> 1;
    const int mBase = blockIdx.y * 128;
    const int nBase = blockIdx.x * 128;

    float acc[4][4][4];
#pragma unroll
    for (int i = 0; i < 4; ++i)
#pragma unroll
        for (int j = 0; j < 4; ++j)
#pragma unroll
            for (int q = 0; q < 4; ++q) acc[i][j][q] = 0.0f;

    const int lrow = lane & 7;
    const int lsel = lane >> 3;
    const int a_r_off = ((lsel & 1) << 3) + lrow;
    const int a_k_off = (lsel & 2) << 2;
    const int b_k_off = (lane & 8);

    const int ldRow = tid >> 1;
    const int ldQ   = (tid & 1) * 4;

    for (int c = 0; c < 4; ++c) {
        const uint4* pahi = (const uint4*)(g_xhi + (size_t)(mBase + ldRow) * DIN + c * 64);
        const uint4* palo = (const uint4*)(g_xlo + (size_t)(mBase + ldRow) * DIN + c * 64);
        const uint4* pbhi = (const uint4*)(g_whi + (size_t)(nBase + ldRow) * DIN + c * 64);
        const uint4* pblo = (const uint4*)(g_wlo + (size_t)(nBase + ldRow) * DIN + c * 64);
        if (c > 0) __syncthreads();
#pragma unroll
        for (int i = 0; i < 4; ++i) {
            uint32_t off = ldRow * 128 + (ldQ + i) * 16;
            uint32_t sw  = off ^ ((off >> 3) & 0x70);
            *(uint4*)(smem + SM_AHI + sw) = pahi[ldQ + i];
            *(uint4*)(smem + SM_ALO + sw) = palo[ldQ + i];
            *(uint4*)(smem + SM_BHI + sw) = pbhi[ldQ + i];
            *(uint4*)(smem + SM_BLO + sw) = pblo[ldQ + i];
        }
        __syncthreads();

#pragma unroll
        for (int pass = 0; pass < 3; ++pass) {
            const uint32_t abase = sb + ((pass < 2) ? SM_AHI : SM_ALO);
            const uint32_t bbase = sb + ((pass == 1) ? SM_BLO : SM_BHI);
#pragma unroll
            for (int k16 = 0; k16 < 4; ++k16) {
                uint32_t afr[4][4];
#pragma unroll
                for (int mf = 0; mf < 4; ++mf) {
                    int r  = wm * 64 + mf * 16 + a_r_off;
                    int kk = k16 * 16 + a_k_off;
                    uint32_t off = r * 128 + kk * 2;
                    off ^= (off >> 3) & 0x70;
                    ldmx4(afr[mf], abase + off);
                }
                uint32_t bfr[4][2];
#pragma unroll
                for (int nf = 0; nf < 4; ++nf) {
                    int r  = wn * 32 + nf * 8 + lrow;
                    int kk = k16 * 16 + b_k_off;
                    uint32_t off = r * 128 + kk * 2;
                    off ^= (off >> 3) & 0x70;
                    ldmx2(bfr[nf], bbase + off);
                }
#pragma unroll
                for (int mf = 0; mf < 4; ++mf)
#pragma unroll
                    for (int nf = 0; nf < 4; ++nf)
                        mma_bf16(acc[mf][nf], afr[mf], bfr[nf]);
            }
        }
    }

#pragma unroll
    for (int nf = 0; nf < 4; ++nf) {
        int n = nBase + wn * 32 + nf * 8 + (lane & 3) * 2;
        float b0 = g_ball[n], b1 = g_ball[n + 1];
#pragma unroll
        for (int mf = 0; mf < 4; ++mf) {
            int r0 = mBase + wm * 64 + mf * 16 + (lane >> 2);
            float2 v0 = make_float2(acc[mf][nf][0] + b0, acc[mf][nf][1] + b1);
            float2 v1 = make_float2(acc[mf][nf][2] + b0, acc[mf][nf][3] + b1);
            *(float2*)&g_xg[(size_t)r0 * NGATE4 + n]       = v0;
            *(float2*)&g_xg[(size_t)(r0 + 8) * NGATE4 + n] = v1;
        }
    }
}

// ======================= recurrent kernel: HMMA + cp.async ==================
#define HS_HI 0
#define HS_LO 65536
#define WS_HI 131072
#define WS_LO 147456
#define GS_OFF 163840
#define SM_REC_TOTAL (GS_OFF + 64 * GSP * 4)

__global__ __launch_bounds__(256, 1) void lstm_rec_mma_kernel(
    const float* __restrict__ Wf, const float* __restrict__ Wi,
    const float* __restrict__ Wg, const float* __restrict__ Wo,
    float* __restrict__ out)
{
    extern __shared__ char sm[];
    const uint32_t sb = smem_u32(sm);
    float* gs = (float*)(sm + GS_OFF);

    const int tid  = threadIdx.x;
    const int lane = tid & 31;
    const int wid  = tid >> 5;
    const int wm   = wid & 3;
    const int wn   = wid >> 2;
    const int cb   = blockIdx.x;
    const int u0   = cb * 4;

    // --- prologue: load + split W recurrent slice into SW128 chunks ---
    for (int it = 0; it < 32; ++it) {
        int idx = it * 256 + tid;
        int r = idx >> 9;
        int k = idx & 511;
        int g = r >> 2, j = r & 3;
        const float* Wp = (g == 0) ? Wf : (g == 1) ? Wi : (g == 2) ? Wg : Wo;
        float w = Wp[(size_t)(u0 + j) * KDH + DIN + k];
        __nv_bfloat16 whi = __float2bfloat16(w);
        __nv_bfloat16 wlo = __float2bfloat16(w - __bfloat162float(whi));
        uint32_t off = r * 128 + (k & 63) * 2;
        off ^= (off >> 3) & 0x70;
        off += (k >> 6) * 2048;
        *(__nv_bfloat16*)(sm + WS_HI + off) = whi;
        *(__nv_bfloat16*)(sm + WS_LO + off) = wlo;
    }
    __syncthreads();

    // --- preload B fragments (constant over all steps) ---
    const int lrow = lane & 7;
    const int lsel = lane >> 3;
    uint32_t bhi[32][2], blo[32][2];
#pragma unroll
    for (int kk = 0; kk < 32; ++kk) {
        uint32_t off = (wn * 8 + lrow) * 128 + ((kk & 3) * 16 + (lane & 8)) * 2;
        off ^= (off >> 3) & 0x70;
        uint32_t base = (kk >> 2) * 2048 + off;
        ldmx2(bhi[kk], sb + WS_HI + base);
        ldmx2(blo[kk], sb + WS_LO + base);
    }

    const int a_r = wm * 16 + ((lsel & 1) << 3) + lrow;
    const int a_k = (lsel & 2) << 2;
    const int eb = tid >> 2;
    const int ej = tid & 3;

    // --- t-invariant staging offsets: 16 x 16B units of one h plane ---
    uint32_t soff[16];   // smem dst (relative, hi plane; lo = +65536)
    uint32_t goff[16];   // gmem element offset (bf16 elements)
#pragma unroll
    for (int i = 0; i < 16; ++i) {
        int idx = i * 256 + tid;        // 0..4095
        int row = idx >> 6;             // 0..63
        int u   = idx & 63;             // 16B unit within row
        uint32_t off = row * 128 + (u & 7) * 16;
        off ^= (off >> 3) & 0x70;
        soff[i] = (u >> 3) * 8192 + off;
        goff[i] = row * HID + u * 8;
    }

    float c_reg = 0.0f;
    float h_last = 0.0f;

    for (int t = 0; t < T_STEPS; ++t) {
        // prefetch xg (independent of barrier)
        const float* xr = g_xg + (size_t)(t * BATCH + eb) * NGATE4 + u0 + ej;
        float xf = xr[0 * HID], xi = xr[1 * HID], xg2 = xr[2 * HID], xo = xr[3 * HID];

        // ---- acquire ----
        if (t > 0) {
            if (tid == 0) {
                unsigned target = (unsigned)t * 128u;
                while (*(volatile unsigned*)&g_ctr < target) { }
                __threadfence();
            }
            __syncthreads();
        }

        const __nv_bfloat16* hhi = g_hbhi[t & 1];
        const __nv_bfloat16* hlo = g_hblo[t & 1];

        // ---- stage full h (both planes) via cp.async, ONE sync ----
#pragma unroll
        for (int i = 0; i < 16; ++i) {
            cp16(sb + HS_HI + soff[i], hhi + goff[i]);
            cp16(sb + HS_LO + soff[i], hlo + goff[i]);
        }
        cp_wait_all();
        __syncthreads();

        // ---- mma chain: 8 chunks x 4 k16, 3 passes ----
        float c4[4] = {0.f, 0.f, 0.f, 0.f};
#pragma unroll
        for (int c = 0; c < 8; ++c) {
#pragma unroll
            for (int q = 0; q < 4; ++q) {
                const int kk = c * 4 + q;
                uint32_t off = a_r * 128 + (q * 16 + a_k) * 2;
                off ^= (off >> 3) & 0x70;
                uint32_t ahi4[4], alo4[4];
                ldmx4(ahi4, sb + HS_HI + c * 8192 + off);
                ldmx4(alo4, sb + HS_LO + c * 8192 + off);
                mma_bf16(c4, ahi4, bhi[kk]);
                mma_bf16(c4, ahi4, blo[kk]);
                mma_bf16(c4, alo4, bhi[kk]);
            }
        }

        // ---- epilogue: fragments -> gs ----
        {
            int row = wm * 16 + (lane >> 2);
            int col = wn * 8 + (lane & 3) * 2;
            *(float2*)&gs[row * GSP + col]       = make_float2(c4[0], c4[1]);
            *(float2*)&gs[(row + 8) * GSP + col] = make_float2(c4[2], c4[3]);
        }
        __syncthreads();

        // ---- elementwise LSTM cell ----
        float pf = gs[eb * GSP + 0  + ej] + xf;
        float pi = gs[eb * GSP + 4  + ej] + xi;
        float pg = gs[eb * GSP + 8  + ej] + xg2;
        float po = gs[eb * GSP + 12 + ej] + xo;
        float fg = fsigm(pf);
        float ig = fsigm(pi);
        float gg = ftanh(pg);
        float og = fsigm(po);
        c_reg = fg * c_reg + ig * gg;
        float hv = og * ftanh(c_reg);
        h_last = hv;

        __nv_bfloat16 hb = __float2bfloat16(hv);
        __nv_bfloat16 lb = __float2bfloat16(hv - __bfloat162float(hb));
        g_hbhi[(t + 1) & 1][eb * HID + u0 + ej] = hb;
        g_hblo[(t + 1) & 1][eb * HID + u0 + ej] = lb;

        // ---- release ----
        __syncthreads();
        if (tid == 0) {
            __threadfence();
            atomicAdd(&g_ctr, 1u);
        }

        out[(size_t)t * (BATCH * HID) + eb * HID + u0 + ej] = hv;
    }

    const size_t off = (size_t)T_STEPS * BATCH * HID;
    out[off + eb * HID + u0 + ej]               = h_last;
    out[off + BATCH * HID + eb * HID + u0 + ej] = c_reg;
}

extern "C" void kernel_launch(void* const* d_in, const int* in_sizes, int n_in,
                              void* d_out, int out_size) {
    const float* X  = (const float*)d_in[0];
    const float* Wf = (const float*)d_in[1];
    const float* bf = (const float*)d_in[2];
    const float* Wi = (const float*)d_in[3];
    const float* bi = (const float*)d_in[4];
    const float* Wg = (const float*)d_in[5];
    const float* bg = (const float*)d_in[6];
    const float* Wo = (const float*)d_in[7];
    const float* bo = (const float*)d_in[8];
    float* out = (float*)d_out;

    cudaFuncSetAttribute(xgemm_mma_kernel,
                         cudaFuncAttributeMaxDynamicSharedMemorySize, SM_MMA_TOTAL);
    cudaFuncSetAttribute(lstm_rec_mma_kernel,
                         cudaFuncAttributeMaxDynamicSharedMemorySize, SM_REC_TOTAL);

    init_kernel<<<64, 256>>>();
    split_kernel<<<1024, 256>>>(X, Wf, bf, Wi, bi, Wg, bg, Wo, bo);
    xgemm_mma_kernel<<<dim3(16, 256), 256, SM_MMA_TOTAL>>>();
    lstm_rec_mma_kernel<<<128, 256, SM_REC_TOTAL>>>(Wf, Wi, Wg, Wo, out);
}